// round 16
// baseline (speedup 1.0000x reference)
#include <cuda_runtime.h>
#include <cuda_bf16.h>
#include <cstdint>

// MaxUnpooling2D scatter-add: ONE fused kernel; zeroing by TMA bulk stores
// issued from 1-in-16 "provider" CTAs (no LSU wavefront theft), self-paced
// gating (no phase tails, no lead-in kernels).
// updates: [16,128,128,64] f32   d_in[0]
// mask:    [16,128,128,64] int32 d_in[1], values in [0, 1<<22)
// out:     [16,256,256,64] f32   (256 MB)

static constexpr int NCTA           = 16384;   // 4M float4-groups / 256
static constexpr int CTAS_PER_BATCH = 1024;
static constexpr int CHUNK_BYTES    = 16384;   // one bulk store
static constexpr int CHUNKS_PER_PROV= 16;      // provider covers 256KB
static constexpr int PROV_PER_BATCH = 64;      // 64 x 256KB = 16MB window
static constexpr size_t BATCH_BYTES = (size_t)1 << 24;   // 16MB

__device__ unsigned g_zcnt[16];
__device__ unsigned g_fin;

__global__ __launch_bounds__(256, 8)
void unpool_fused_tma(const float4* __restrict__ up,
                      const int4*   __restrict__ mk,
                      float*        __restrict__ out)
{
    __shared__ __align__(128) char sbuf[CHUNK_BYTES];

    const unsigned bid = blockIdx.x;
    const int      tx  = threadIdx.x;
    const unsigned b   = bid >> 10;             // my scatter batch
    const unsigned l   = bid & 1023u;           // local id within batch group
    const bool     prov = (l & 15u) == 0u;      // provider CTA (1 in 16)
    const unsigned pidx = l >> 4;               // provider index 0..63

    // ---- Providers: zero smem once, TMA-bulk-store 256KB per target batch
    if (prov && (b == 0 || bid < NCTA - CTAS_PER_BATCH)) {
        float4 zv = make_float4(0.f, 0.f, 0.f, 0.f);
        #pragma unroll
        for (int j = 0; j < (CHUNK_BYTES / 16) / 256; j++)   // 4x
            ((float4*)sbuf)[j * 256 + tx] = zv;
        __syncthreads();
        asm volatile("fence.proxy.async.shared::cta;" ::: "memory");

        if (tx == 0) {
            uint32_t saddr;
            asm("{ .reg .u64 t; cvta.to.shared.u64 t, %1; cvt.u32.u64 %0, t; }"
                : "=r"(saddr) : "l"(sbuf));
            // target batch b+1 (and batch 0 itself for group 0)
            char* base1 = (char*)out + (size_t)(b + 1) * BATCH_BYTES
                          + (size_t)pidx * (CHUNK_BYTES * CHUNKS_PER_PROV);
            if (b == 0) {
                char* base0 = (char*)out
                              + (size_t)pidx * (CHUNK_BYTES * CHUNKS_PER_PROV);
                #pragma unroll
                for (int c = 0; c < CHUNKS_PER_PROV; c++)
                    asm volatile(
                        "cp.async.bulk.global.shared::cta.bulk_group [%0], [%1], %2;"
                        :: "l"(base0 + (size_t)c * CHUNK_BYTES), "r"(saddr),
                           "r"((unsigned)CHUNK_BYTES) : "memory");
            }
            if (bid < NCTA - CTAS_PER_BATCH) {
                #pragma unroll
                for (int c = 0; c < CHUNKS_PER_PROV; c++)
                    asm volatile(
                        "cp.async.bulk.global.shared::cta.bulk_group [%0], [%1], %2;"
                        :: "l"(base1 + (size_t)c * CHUNK_BYTES), "r"(saddr),
                           "r"((unsigned)CHUNK_BYTES) : "memory");
            }
            asm volatile("cp.async.bulk.commit_group;" ::: "memory");
            asm volatile("cp.async.bulk.wait_group 0;" ::: "memory");
            __threadfence();                     // release bulk writes
            if (b == 0)                      atomicAdd(&g_zcnt[0], 1u);
            if (bid < NCTA - CTAS_PER_BATCH) atomicAdd(&g_zcnt[b + 1], 1u);
        }
    }

    // ---- Gate: my batch fully zeroed? ----
    if (tx == 0) {
        volatile unsigned* p = &g_zcnt[b];
        if (*p < PROV_PER_BATCH) {
            unsigned ns = 32;
            do { __nanosleep(ns); if (ns < 512) ns <<= 1; }
            while (*p < PROV_PER_BATCH);
        }
    }
    __syncthreads();

    // ---- Scatter: one float4-group per thread (4 spread REDG) ----
    {
        unsigned g = bid * 256u + tx;
        float* outb = out + ((size_t)b << 22);
        float4 u = up[g];
        int4   m = mk[g];
        atomicAdd(outb + m.x, u.x);
        atomicAdd(outb + m.y, u.y);
        atomicAdd(outb + m.z, u.z);
        atomicAdd(outb + m.w, u.w);
    }

    // ---- Reset counters for next graph replay (last CTA) ----
    __syncthreads();
    if (tx == 0) {
        unsigned v = atomicAdd(&g_fin, 1u);
        if (v == NCTA - 1) {
            #pragma unroll
            for (int i = 0; i < 16; i++) g_zcnt[i] = 0;
            g_fin = 0;
            __threadfence();
        }
    }
}

extern "C" void kernel_launch(void* const* d_in, const int* in_sizes, int n_in,
                              void* d_out, int out_size) {
    const float4* up  = (const float4*)d_in[0];
    const int4*   mk  = (const int4*)d_in[1];
    float*        out = (float*)d_out;

    unpool_fused_tma<<<NCTA, 256>>>(up, mk, out);
}